// round 11
// baseline (speedup 1.0000x reference)
#include <cuda_runtime.h>

#define N_VOX 1000000
#define KVOL  27
#define C_IN  3
#define C_HID 64
#define C_OUT 3
#define BN_EPS 1e-5f
#define PBLK  128   // points per block; 8 warps x 16 points each
#define IDMASK 0x1FFFFFF

// Scratch (device globals: allocation-free per harness rules)
__device__ float g_h[(size_t)N_VOX * C_HID];   // 256 MB: conv1 out (pre-BN)
__device__ float g_stats[4 * C_HID];           // sum, sumsq, scale, shift

typedef unsigned long long u64;

__device__ __forceinline__ u64 pack2(float lo, float hi) {
    u64 r; asm("mov.b64 %0, {%1, %2};" : "=l"(r) : "f"(lo), "f"(hi)); return r;
}
__device__ __forceinline__ void unpack2(u64 v, float& lo, float& hi) {
    asm("mov.b64 {%0, %1}, %2;" : "=f"(lo), "=f"(hi) : "l"(v));
}
#define FMA2(d, a, b, c) asm("fma.rn.f32x2 %0, %1, %2, %3;" : "=l"(d) : "l"(a), "l"(b), "l"(c))

__device__ __forceinline__ u64 relu2(u64 v) {
    float a, b; unpack2(v, a, b);
    return pack2(fmaxf(a, 0.f), fmaxf(b, 0.f));
}

// ---------------------------------------------------------------------------
__global__ void zero_stats_kernel() {
    int i = threadIdx.x;
    if (i < 2 * C_HID) g_stats[i] = 0.f;
}
__global__ void dummy_kernel() {}   // keeps conv1 at ncu capture index 3

// ---------------------------------------------------------------------------
// conv1 (warp-per-point, compacted counted loop):
// h[n,:] = sum_{valid k} feats[nbr[k,n]] @ W1[k]
// Lane owns channel pair `lane` (channels 2*lane, 2*lane+1). Valid (k,id)
// entries are compacted into packed ints, so the hot loop is warp-uniform,
// counted, ffs-free, and 1-deep software-pipelined. Fused BN-stats.
__global__ __launch_bounds__(256) void conv1_kernel(const float* __restrict__ feats,
                                                    const float* __restrict__ W1,
                                                    const int*   __restrict__ nbr) {
    __shared__ u64 w1s[KVOL * 96];        // straight u64 copy of W1: [(k*3+c)*32+p]
    __shared__ int idxs[KVOL * PBLK];     // 13.8 KB
    __shared__ int lst[PBLK * KVOL];      // 13.8 KB packed (k<<25)|id
    __shared__ int cntS[PBLK];
    __shared__ float sm_s[8][C_HID], sm_s2[8][C_HID];
    const int tid = threadIdx.x;
    {
        const u64* w1g = (const u64*)W1;
        for (int i = tid; i < KVOL * 96; i += 256) w1s[i] = w1g[i];
    }
    const int base = blockIdx.x * PBLK;
    for (int i = tid; i < KVOL * PBLK; i += 256) {
        int k = i >> 7, pl = i & 127;
        int n = base + pl;
        idxs[i] = (n < N_VOX) ? __ldg(&nbr[(size_t)k * N_VOX + n]) : -1;
    }
    __syncthreads();
    if (tid < PBLK) {                     // deterministic per-point compaction
        int c = 0;
        #pragma unroll
        for (int k = 0; k < KVOL; k++) {
            int id = idxs[k * PBLK + tid];
            if (id >= 0) lst[tid * KVOL + (c++)] = (k << 25) | id;
        }
        cntS[tid] = c;
    }
    __syncthreads();

    const int lane = tid & 31;
    const int wrp  = tid >> 5;

    float s0 = 0.f, s1 = 0.f, q0 = 0.f, q1 = 0.f;

    #pragma unroll 1
    for (int pp = 0; pp < PBLK / 8; pp++) {        // 16 points per warp
        const int pl = wrp * (PBLK / 8) + pp;
        const int n  = base + pl;
        const int cnt = cntS[pl];
        const int* lp = lst + pl * KVOL;

        u64 acc = 0ull;
        int pk = 0; float g0 = 0.f, g1 = 0.f, g2 = 0.f;
        if (cnt > 0) {
            pk = lp[0];
            int id = pk & IDMASK;
            g0 = __ldg(&feats[3 * id + 0]);
            g1 = __ldg(&feats[3 * id + 1]);
            g2 = __ldg(&feats[3 * id + 2]);
        }
        #pragma unroll 1
        for (int j = 0; j < cnt; j++) {
            int k = pk >> 25;
            float f0 = g0, f1 = g1, f2 = g2;
            if (j + 1 < cnt) {                      // prefetch next entry
                pk = lp[j + 1];
                int id = pk & IDMASK;
                g0 = __ldg(&feats[3 * id + 0]);
                g1 = __ldg(&feats[3 * id + 1]);
                g2 = __ldg(&feats[3 * id + 2]);
            }
            const u64* wk = w1s + k * 96 + lane;
            u64 w0 = wk[0], w1v = wk[32], w2v = wk[64];
            FMA2(acc, pack2(f0, f0), w0,  acc);
            FMA2(acc, pack2(f1, f1), w1v, acc);
            FMA2(acc, pack2(f2, f2), w2v, acc);
        }
        if (n < N_VOX) {
            ((u64*)(g_h + (size_t)n * C_HID))[lane] = acc;   // 256B coalesced
            float h0, h1; unpack2(acc, h0, h1);
            s0 += h0; s1 += h1;
            q0 = fmaf(h0, h0, q0); q1 = fmaf(h1, h1, q1);
        }
    }

    sm_s [wrp][2 * lane] = s0;  sm_s [wrp][2 * lane + 1] = s1;
    sm_s2[wrp][2 * lane] = q0;  sm_s2[wrp][2 * lane + 1] = q1;
    __syncthreads();
    if (tid < C_HID) {
        float t = 0.f, t2 = 0.f;
        #pragma unroll
        for (int w = 0; w < 8; w++) { t += sm_s[w][tid]; t2 += sm_s2[w][tid]; }
        atomicAdd(&g_stats[tid], t);
        atomicAdd(&g_stats[C_HID + tid], t2);
    }
}

// ---------------------------------------------------------------------------
__global__ void finalize_kernel(const float* __restrict__ gamma,
                                const float* __restrict__ beta) {
    int d = threadIdx.x;
    if (d < C_HID) {
        float mu  = g_stats[d] * (1.f / N_VOX);
        float var = g_stats[C_HID + d] * (1.f / N_VOX) - mu * mu;
        float sc  = gamma[d] * rsqrtf(var + BN_EPS);
        g_stats[2 * C_HID + d] = sc;
        g_stats[3 * C_HID + d] = beta[d] - mu * sc;
    }
}

// ---------------------------------------------------------------------------
// conv2 (warp-per-point, compacted counted loop + prefetch):
// out[n] = sum_k relu(bn(h[nbr[k,n]])) @ W2[26-k].  Lane owns channel pair.
__global__ __launch_bounds__(256) void conv2_kernel(const float* __restrict__ W2,
                                                    const int*   __restrict__ nbr,
                                                    float* __restrict__ out) {
    __shared__ u64 w2t[KVOL * 96];        // [(k*3+c)*32+p], wt[k][c][d]=W2[26-k][d][c]
    __shared__ int idxs[KVOL * PBLK];
    __shared__ int lst[PBLK * KVOL];
    __shared__ int cntS[PBLK];
    const int tid = threadIdx.x;
    {
        float* fp = (float*)w2t;
        for (int i = tid; i < KVOL * C_OUT * C_HID; i += 256) {
            int k   = i / (C_OUT * C_HID);
            int rem = i % (C_OUT * C_HID);
            int c   = rem / C_HID;
            int d   = rem % C_HID;
            fp[(k * 3 + c) * C_HID + d] =
                W2[(size_t)(KVOL - 1 - k) * (C_HID * C_OUT) + d * C_OUT + c];
        }
    }
    const int base = blockIdx.x * PBLK;
    for (int i = tid; i < KVOL * PBLK; i += 256) {
        int k = i >> 7, pl = i & 127;
        int n = base + pl;
        idxs[i] = (n < N_VOX) ? __ldg(&nbr[(size_t)k * N_VOX + n]) : -1;
    }
    __syncthreads();
    if (tid < PBLK) {
        int c = 0;
        #pragma unroll
        for (int k = 0; k < KVOL; k++) {
            int id = idxs[k * PBLK + tid];
            if (id >= 0) lst[tid * KVOL + (c++)] = (k << 25) | id;
        }
        cntS[tid] = c;
    }
    __syncthreads();

    const int lane = tid & 31;
    const int wrp  = tid >> 5;

    const u64 scp = pack2(g_stats[2 * C_HID + 2 * lane], g_stats[2 * C_HID + 2 * lane + 1]);
    const u64 shp = pack2(g_stats[3 * C_HID + 2 * lane], g_stats[3 * C_HID + 2 * lane + 1]);

    #pragma unroll 1
    for (int pp = 0; pp < PBLK / 8; pp++) {        // 16 points per warp
        const int pl = wrp * (PBLK / 8) + pp;
        const int n  = base + pl;
        const int cnt = cntS[pl];
        const int* lp = lst + pl * KVOL;

        u64 a0 = 0ull, a1 = 0ull, a2 = 0ull;
        int pk = 0; u64 hp = 0ull;
        if (cnt > 0) {
            pk = lp[0];
            hp = __ldg((const u64*)(g_h + (size_t)(pk & IDMASK) * C_HID) + lane);
        }
        #pragma unroll 1
        for (int j = 0; j < cnt; j++) {
            int k = pk >> 25;
            u64 hv = hp;
            if (j + 1 < cnt) {                      // prefetch next h pair
                pk = lp[j + 1];
                hp = __ldg((const u64*)(g_h + (size_t)(pk & IDMASK) * C_HID) + lane);
            }
            FMA2(hv, hv, scp, shp);
            hv = relu2(hv);
            const u64* wk = w2t + k * 96 + lane;
            FMA2(a0, hv, wk[0],  a0);
            FMA2(a1, hv, wk[32], a1);
            FMA2(a2, hv, wk[64], a2);
        }
        float r0, r1, r2;
        { float lo, hi; unpack2(a0, lo, hi); r0 = lo + hi; }
        { float lo, hi; unpack2(a1, lo, hi); r1 = lo + hi; }
        { float lo, hi; unpack2(a2, lo, hi); r2 = lo + hi; }
        #pragma unroll
        for (int o = 16; o >= 1; o >>= 1) {
            r0 += __shfl_xor_sync(0xffffffffu, r0, o);
            r1 += __shfl_xor_sync(0xffffffffu, r1, o);
            r2 += __shfl_xor_sync(0xffffffffu, r2, o);
        }
        if (lane == 0 && n < N_VOX) {
            out[3 * n + 0] = r0;
            out[3 * n + 1] = r1;
            out[3 * n + 2] = r2;
        }
    }
}

// ---------------------------------------------------------------------------
extern "C" void kernel_launch(void* const* d_in, const int* in_sizes, int n_in,
                              void* d_out, int out_size) {
    const float* feats = (const float*)d_in[0];
    const float* W1    = (const float*)d_in[1];
    const float* gamma = (const float*)d_in[2];
    const float* beta  = (const float*)d_in[3];
    const float* W2    = (const float*)d_in[4];
    const int*   nbr   = (const int*)  d_in[5];
    float*       out   = (float*)d_out;

    const int nblk = (N_VOX + PBLK - 1) / PBLK;

    zero_stats_kernel<<<1, 128>>>();                    // 0
    dummy_kernel<<<1, 32>>>();                          // 1
    dummy_kernel<<<1, 32>>>();                          // 2
    conv1_kernel<<<nblk, 256>>>(feats, W1, nbr);        // 3 <- ncu
    finalize_kernel<<<1, 64>>>(gamma, beta);            // 4
    conv2_kernel<<<nblk, 256>>>(W2, nbr, out);          // 5
}

// round 12
// speedup vs baseline: 1.7086x; 1.7086x over previous
#include <cuda_runtime.h>

#define N_VOX 1000000
#define KVOL  27
#define C_IN  3
#define C_HID 64
#define C_OUT 3
#define BN_EPS 1e-5f
#define PBLK  128   // points per block; warp handles 8 point-pairs (16-lane teams)
#define IDMASK 0x1FFFFFF
#define FULLM 0xffffffffu

// Scratch (device globals: allocation-free per harness rules)
__device__ float g_h[(size_t)N_VOX * C_HID];   // 256 MB: conv1 out (pre-BN)
__device__ float g_stats[4 * C_HID];           // sum, sumsq, scale, shift

typedef unsigned long long u64;

__device__ __forceinline__ u64 pack2(float lo, float hi) {
    u64 r; asm("mov.b64 %0, {%1, %2};" : "=l"(r) : "f"(lo), "f"(hi)); return r;
}
__device__ __forceinline__ void unpack2(u64 v, float& lo, float& hi) {
    asm("mov.b64 {%0, %1}, %2;" : "=f"(lo), "=f"(hi) : "l"(v));
}
#define FMA2(d, a, b, c) asm("fma.rn.f32x2 %0, %1, %2, %3;" : "=l"(d) : "l"(a), "l"(b), "l"(c))

__device__ __forceinline__ u64 relu2(u64 v) {
    float a, b; unpack2(v, a, b);
    return pack2(fmaxf(a, 0.f), fmaxf(b, 0.f));
}

// ---------------------------------------------------------------------------
__global__ void zero_stats_kernel() {
    int i = threadIdx.x;
    if (i < 2 * C_HID) g_stats[i] = 0.f;
}
__global__ void dummy_kernel() {}   // keeps conv1 at ncu capture index 3

// ---------------------------------------------------------------------------
// conv1 (pair teams, convergent shfl-batch loop):
// h[n,:] = sum_{valid k} feats[nbr[k,n]] @ W1[k]
// Per point: compacted (k,id) list. Lanes pre-gather up to 16 entries' feats in
// parallel (invalid -> 0), then a warp-uniform counted loop broadcasts each
// entry via shfl and does smem-weight FMAs. No LDG in the serial chain.
__global__ __launch_bounds__(256, 6) void conv1_kernel(const float* __restrict__ feats,
                                                       const float* __restrict__ W1,
                                                       const int*   __restrict__ nbr) {
    __shared__ ulonglong2 w1p[KVOL * 48];   // 20.7 KB  [(k*3+c)*16 + tl]
    __shared__ int lst[PBLK * 28];          // 14.3 KB packed (k<<25)|id
    __shared__ int cnts[PBLK];
    __shared__ float st_sm[2 * C_HID];
    const int tid = threadIdx.x;
    {
        const u64* w1g = (const u64*)W1;    // pair index = (k*3+c)*32 + p
        for (int i = tid; i < KVOL * 48; i += 256) {
            int kc = i >> 4, t = i & 15;
            int b = kc * 32 + 2 * t;
            w1p[i] = make_ulonglong2(w1g[b], w1g[b + 1]);
        }
    }
    if (tid < 2 * C_HID) st_sm[tid] = 0.f;
    const int base = blockIdx.x * PBLK;
    if (tid < PBLK) {                       // per-point compaction
        int n = base + tid, c = 0;
        if (n < N_VOX) {
            #pragma unroll
            for (int k = 0; k < KVOL; k++) {
                int id = __ldg(&nbr[(size_t)k * N_VOX + n]);
                if (id >= 0) lst[tid * 28 + (c++)] = (k << 25) | id;
            }
        }
        cnts[tid] = c;
    }
    __syncthreads();

    const int lane   = tid & 31;
    const int wrp    = tid >> 5;
    const int tlane  = lane & 15;
    const int half16 = lane & 16;

    float s0 = 0.f, s1 = 0.f, s2v = 0.f, s3 = 0.f;
    float q0 = 0.f, q1 = 0.f, q2 = 0.f, q3 = 0.f;

    #pragma unroll 1
    for (int pp = 0; pp < PBLK / 16; pp++) {        // 8 point-pairs per warp
        const int pl = wrp * 16 + pp * 2 + (half16 >> 4);
        const int n  = base + pl;
        const int cnt = cnts[pl];
        const int cmax = max(cnt, __shfl_xor_sync(FULLM, cnt, 16));
        const int* lp = lst + pl * 28;

        u64 acc0 = 0ull, acc1 = 0ull;               // lane's channels 4t..4t+3
        #pragma unroll 1
        for (int b = 0; b < cmax; b += 16) {
            int j = b + tlane;
            int pk = (j < cnt) ? lp[j] : 0;
            int kk = pk >> 25;
            float f0 = 0.f, f1 = 0.f, f2 = 0.f;
            if (j < cnt) {                          // 16-wide parallel gather
                int id = pk & IDMASK;
                f0 = __ldg(&feats[3 * id + 0]);
                f1 = __ldg(&feats[3 * id + 1]);
                f2 = __ldg(&feats[3 * id + 2]);
            }
            const int nb = min(cmax - b, 16);
            #pragma unroll 1
            for (int jj = 0; jj < nb; jj++) {       // convergent, short-latency
                int srcl = half16 + jj;
                int k    = __shfl_sync(FULLM, kk, srcl);
                float e0 = __shfl_sync(FULLM, f0, srcl);
                float e1 = __shfl_sync(FULLM, f1, srcl);
                float e2 = __shfl_sync(FULLM, f2, srcl);
                const ulonglong2* wp = w1p + k * 48 + tlane;
                ulonglong2 w0 = wp[0], w1v = wp[16], w2v = wp[32];
                u64 a0 = pack2(e0, e0), a1 = pack2(e1, e1), a2 = pack2(e2, e2);
                FMA2(acc0, a0, w0.x,  acc0); FMA2(acc1, a0, w0.y,  acc1);
                FMA2(acc0, a1, w1v.x, acc0); FMA2(acc1, a1, w1v.y, acc1);
                FMA2(acc0, a2, w2v.x, acc0); FMA2(acc1, a2, w2v.y, acc1);
            }
        }
        if (n < N_VOX) {
            ulonglong2* ho = (ulonglong2*)(g_h + (size_t)n * C_HID) + tlane;
            *ho = make_ulonglong2(acc0, acc1);
            float h0, h1, h2, h3;
            unpack2(acc0, h0, h1);
            unpack2(acc1, h2, h3);
            s0 += h0; s1 += h1; s2v += h2; s3 += h3;
            q0 = fmaf(h0, h0, q0); q1 = fmaf(h1, h1, q1);
            q2 = fmaf(h2, h2, q2); q3 = fmaf(h3, h3, q3);
        }
    }

    // stats: smem atomics (distinct addr per tlane; light contention)
    atomicAdd(&st_sm[4 * tlane + 0], s0);
    atomicAdd(&st_sm[4 * tlane + 1], s1);
    atomicAdd(&st_sm[4 * tlane + 2], s2v);
    atomicAdd(&st_sm[4 * tlane + 3], s3);
    atomicAdd(&st_sm[C_HID + 4 * tlane + 0], q0);
    atomicAdd(&st_sm[C_HID + 4 * tlane + 1], q1);
    atomicAdd(&st_sm[C_HID + 4 * tlane + 2], q2);
    atomicAdd(&st_sm[C_HID + 4 * tlane + 3], q3);
    __syncthreads();
    if (tid < 2 * C_HID) atomicAdd(&g_stats[tid], st_sm[tid]);
}

// ---------------------------------------------------------------------------
__global__ void finalize_kernel(const float* __restrict__ gamma,
                                const float* __restrict__ beta) {
    int d = threadIdx.x;
    if (d < C_HID) {
        float mu  = g_stats[d] * (1.f / N_VOX);
        float var = g_stats[C_HID + d] * (1.f / N_VOX) - mu * mu;
        float sc  = gamma[d] * rsqrtf(var + BN_EPS);
        g_stats[2 * C_HID + d] = sc;
        g_stats[3 * C_HID + d] = beta[d] - mu * sc;
    }
}

// ---------------------------------------------------------------------------
// conv2 (pair teams, compacted counted loop):
// out[n] = sum_k relu(bn(h[nbr[k,n]])) @ W2[26-k]
// Counted loop (no ffs chain) lets ptxas pipeline h-gather LDGs across
// iterations; BN+ReLU in registers; higher occupancy via launch_bounds(,6).
__global__ __launch_bounds__(256, 6) void conv2_kernel(const float* __restrict__ W2,
                                                       const int*   __restrict__ nbr,
                                                       float* __restrict__ out) {
    __shared__ ulonglong2 w2p[KVOL * 48];   // plane: [(k*3+c)*16 + tl]
    __shared__ int lst[PBLK * 28];
    __shared__ int cnts[PBLK];
    const int tid = threadIdx.x;
    {
        // wt[k][c][d] = W2[26-k][d][c]; lane tl gets channels 4tl..4tl+3
        float* fp = (float*)w2p;
        for (int i = tid; i < KVOL * C_OUT * C_HID; i += 256) {
            int k   = i / (C_OUT * C_HID);
            int rem = i % (C_OUT * C_HID);
            int c   = rem / C_HID;
            int d   = rem % C_HID;
            float v = W2[(size_t)(KVOL - 1 - k) * (C_HID * C_OUT) + d * C_OUT + c];
            int t = d >> 2, j = d & 3;
            fp[((k * 3 + c) * 16 + t) * 4 + j] = v;
        }
    }
    const int base = blockIdx.x * PBLK;
    if (tid < PBLK) {
        int n = base + tid, c = 0;
        if (n < N_VOX) {
            #pragma unroll
            for (int k = 0; k < KVOL; k++) {
                int id = __ldg(&nbr[(size_t)k * N_VOX + n]);
                if (id >= 0) lst[tid * 28 + (c++)] = (k << 25) | id;
            }
        }
        cnts[tid] = c;
    }
    __syncthreads();

    const int lane   = tid & 31;
    const int wrp    = tid >> 5;
    const int tlane  = lane & 15;
    const int half16 = lane & 16;

    const u64 scA = pack2(g_stats[2 * C_HID + 4 * tlane + 0], g_stats[2 * C_HID + 4 * tlane + 1]);
    const u64 scB = pack2(g_stats[2 * C_HID + 4 * tlane + 2], g_stats[2 * C_HID + 4 * tlane + 3]);
    const u64 shA = pack2(g_stats[3 * C_HID + 4 * tlane + 0], g_stats[3 * C_HID + 4 * tlane + 1]);
    const u64 shB = pack2(g_stats[3 * C_HID + 4 * tlane + 2], g_stats[3 * C_HID + 4 * tlane + 3]);

    #pragma unroll 1
    for (int pp = 0; pp < PBLK / 16; pp++) {        // 8 point-pairs per warp
        const int pl = wrp * 16 + pp * 2 + (half16 >> 4);
        const int n  = base + pl;
        const int cnt = cnts[pl];
        const int* lp = lst + pl * 28;

        u64 acc0 = 0ull, acc1 = 0ull, acc2 = 0ull;
        #pragma unroll 2
        for (int j = 0; j < cnt; j++) {
            int pk = lp[j];
            int k  = pk >> 25;
            int id = pk & IDMASK;
            ulonglong2 hv = __ldg((const ulonglong2*)(g_h + (size_t)id * C_HID) + tlane);
            FMA2(hv.x, hv.x, scA, shA);
            FMA2(hv.y, hv.y, scB, shB);
            hv.x = relu2(hv.x);
            hv.y = relu2(hv.y);
            const ulonglong2* wp = w2p + k * 48 + tlane;
            ulonglong2 w0 = wp[0], w1 = wp[16], w2v = wp[32];
            FMA2(acc0, hv.x, w0.x,  acc0); FMA2(acc0, hv.y, w0.y,  acc0);
            FMA2(acc1, hv.x, w1.x,  acc1); FMA2(acc1, hv.y, w1.y,  acc1);
            FMA2(acc2, hv.x, w2v.x, acc2); FMA2(acc2, hv.y, w2v.y, acc2);
        }
        float r0, r1, r2;
        { float lo, hi; unpack2(acc0, lo, hi); r0 = lo + hi; }
        { float lo, hi; unpack2(acc1, lo, hi); r1 = lo + hi; }
        { float lo, hi; unpack2(acc2, lo, hi); r2 = lo + hi; }
        #pragma unroll
        for (int o = 8; o >= 1; o >>= 1) {
            r0 += __shfl_xor_sync(FULLM, r0, o);
            r1 += __shfl_xor_sync(FULLM, r1, o);
            r2 += __shfl_xor_sync(FULLM, r2, o);
        }
        if (tlane == 0 && n < N_VOX) {
            out[3 * n + 0] = r0;
            out[3 * n + 1] = r1;
            out[3 * n + 2] = r2;
        }
    }
}

// ---------------------------------------------------------------------------
extern "C" void kernel_launch(void* const* d_in, const int* in_sizes, int n_in,
                              void* d_out, int out_size) {
    const float* feats = (const float*)d_in[0];
    const float* W1    = (const float*)d_in[1];
    const float* gamma = (const float*)d_in[2];
    const float* beta  = (const float*)d_in[3];
    const float* W2    = (const float*)d_in[4];
    const int*   nbr   = (const int*)  d_in[5];
    float*       out   = (float*)d_out;

    const int nblk = (N_VOX + PBLK - 1) / PBLK;

    zero_stats_kernel<<<1, 128>>>();                    // 0
    dummy_kernel<<<1, 32>>>();                          // 1
    dummy_kernel<<<1, 32>>>();                          // 2
    conv1_kernel<<<nblk, 256>>>(feats, W1, nbr);        // 3 <- ncu
    finalize_kernel<<<1, 64>>>(gamma, beta);            // 4
    conv2_kernel<<<nblk, 256>>>(W2, nbr, out);          // 5
}